// round 6
// baseline (speedup 1.0000x reference)
#include <cuda_runtime.h>

#define NVOX (128*128*128)
#define EPSV 1e-5f
#define SLOPE 0.01f

// Scratch (device globals: no allocation allowed in kernel_launch)
static __device__ float g_buf0[16*NVOX];   // 128 MB
static __device__ float g_buf1[16*NVOX];   // 128 MB
static __device__ __align__(16) unsigned char g_mask[NVOX];
static __device__ __align__(16) float g_wpack[4][6912];  // weights [tap][c][o]
static __device__ float g_sum[5][16];
static __device__ float g_sq[5][16];
static __device__ int   g_cnt;

__device__ __forceinline__ unsigned long long ffma2(unsigned long long a,
                                                    unsigned long long b,
                                                    unsigned long long c){
  unsigned long long d;
  asm("fma.rn.f32x2 %0, %1, %2, %3;" : "=l"(d) : "l"(a), "l"(b), "l"(c));
  return d;
}
__device__ __forceinline__ unsigned long long dup2(float x){
  unsigned long long d;
  asm("mov.b64 %0, {%1, %1};" : "=l"(d) : "f"(x));
  return d;
}
__device__ __forceinline__ float2 unpack2(unsigned long long v){
  float2 r; asm("mov.b64 {%0, %1}, %2;" : "=f"(r.x), "=f"(r.y) : "l"(v));
  return r;
}

__device__ __forceinline__ float warp_sum(float v){
#pragma unroll
  for (int o = 16; o; o >>= 1) v += __shfl_xor_sync(0xffffffffu, v, o);
  return v;
}

__global__ void k_zero(){
  int t = threadIdx.x;
  if (t < 80){ (&g_sum[0][0])[t] = 0.f; (&g_sq[0][0])[t] = 0.f; }
  if (t == 0) g_cnt = 0;
}

// Repack 3x3x3 weights [o][c][tap] -> [tap][c][o] (one block per layer)
__global__ void k_pack(const float* __restrict__ w1, const float* __restrict__ w2,
                       const float* __restrict__ w3, const float* __restrict__ w4){
  const float* w = blockIdx.x == 0 ? w1 : blockIdx.x == 1 ? w2 :
                   blockIdx.x == 2 ? w3 : w4;
  for (int i = threadIdx.x; i < 6912; i += 256){
    int o = i & 15, c = (i >> 4) & 15, tap = i >> 8;
    g_wpack[blockIdx.x][i] = w[(o*16 + c)*27 + tap];
  }
}

// Layer 0: mask gen + active count + 1x1 conv (4->16) + masked stats
__global__ void __launch_bounds__(256) k_init(
    const float* __restrict__ feat, const int* __restrict__ maski,
    const float* __restrict__ w0, const float* __restrict__ b0)
{
  __shared__ float s_w[64];   // [c][o]
  __shared__ float s_b[16];
  __shared__ float s_red[32];
  __shared__ int s_cnt;
  int tid = threadIdx.x;
  if (tid < 64) s_w[tid] = w0[(tid & 15) * 4 + (tid >> 4)];
  if (tid < 16) s_b[tid] = b0[tid];
  if (tid < 32) s_red[tid] = 0.f;
  if (tid == 0) s_cnt = 0;
  __syncthreads();

  int p = (blockIdx.x * 256 + tid) * 4;
  float xf[4][4];
#pragma unroll
  for (int c = 0; c < 4; c++){
    float4 t4 = *(const float4*)(feat + c * NVOX + p);
    xf[c][0] = t4.x; xf[c][1] = t4.y; xf[c][2] = t4.z; xf[c][3] = t4.w;
  }
  int4 mi = *(const int4*)(maski + p);
  float m[4] = { mi.x > 0 ? 1.f : 0.f, mi.y > 0 ? 1.f : 0.f,
                 mi.z > 0 ? 1.f : 0.f, mi.w > 0 ? 1.f : 0.f };
  *(uchar4*)(g_mask + p) = make_uchar4((unsigned char)m[0], (unsigned char)m[1],
                                       (unsigned char)m[2], (unsigned char)m[3]);
  int cnt = (int)(m[0] + m[1] + m[2] + m[3]);

  float ps[16], pq[16];
#pragma unroll
  for (int o = 0; o < 16; o++){
    float y[4];
#pragma unroll
    for (int v = 0; v < 4; v++){
      float a = s_b[o];
#pragma unroll
      for (int c = 0; c < 4; c++) a = fmaf(s_w[c*16 + o], xf[c][v], a);
      y[v] = a * m[v];
    }
    *(float4*)(g_buf0 + o*NVOX + p) = make_float4(y[0], y[1], y[2], y[3]);
    ps[o] = (y[0] + y[1]) + (y[2] + y[3]);
    pq[o] = (y[0]*y[0] + y[1]*y[1]) + (y[2]*y[2] + y[3]*y[3]);
  }
#pragma unroll
  for (int o = 0; o < 16; o++){
    float s = warp_sum(ps[o]);
    float q = warp_sum(pq[o]);
    if ((tid & 31) == 0){ atomicAdd(&s_red[o], s); atomicAdd(&s_red[16 + o], q); }
  }
  {
    int c2 = cnt;
#pragma unroll
    for (int o = 16; o; o >>= 1) c2 += __shfl_xor_sync(0xffffffffu, c2, o);
    if ((tid & 31) == 0) atomicAdd(&s_cnt, c2);
  }
  __syncthreads();
  if (tid < 16)      atomicAdd(&g_sum[0][tid], s_red[tid]);
  else if (tid < 32) atomicAdd(&g_sq[0][tid - 16], s_red[tid]);
  if (tid == 0) atomicAdd(&g_cnt, s_cnt);
}

// 3x3x3 subm conv, fused BN+LeakyReLU+mask on smem fill, masked raw output,
// stats accumulated. 256 threads, tile 16x8x8, 4 voxels/thread (2x * 2z),
// channel chunks of 8. FFMA2-packed over output-channel pairs; weight LDS
// amortized over 4 voxels.
// smem (floats): s_w[0,6912) s_in[6912,22112)=[c8][z10][y10][x19]
//   s_a[22112,22128) s_c[22128,22144) s_b[22144,22160) s_red[22160,22192)
__global__ void __launch_bounds__(256, 2) k_conv(
    int dir, int stage,
    const float* __restrict__ b,
    const float* __restrict__ gamma_p, const float* __restrict__ beta_p)
{
  extern __shared__ float sm[];
  float* s_w   = sm;
  float* s_in  = sm + 6912;
  float* s_a   = sm + 22112;
  float* s_c   = s_a + 16;
  float* s_b   = s_c + 16;     // float offset 22144 (8B-aligned)
  float* s_red = s_b + 16;     // [22160,22192)

  const float* in  = dir ? g_buf1 : g_buf0;
  float*       out = dir ? g_buf0 : g_buf1;
  const float* sum_p = g_sum[stage - 1];
  const float* sq_p  = g_sq[stage - 1];
  float* sum_c = g_sum[stage];
  float* sq_c  = g_sq[stage];

  int tid = threadIdx.x;
  if (tid < 16){
    float n = (float)g_cnt;
    float mean = sum_p[tid] / n;
    float var = sq_p[tid] / n - mean * mean;
    float a = gamma_p[tid] * rsqrtf(var + EPSV);
    s_a[tid] = a;
    s_c[tid] = beta_p[tid] - mean * a;
    s_b[tid] = b[tid];
  }
  if (tid < 32) s_red[tid] = 0.f;
  {
    const float* wsrc = g_wpack[stage - 1];
    for (int i = tid * 4; i < 6912; i += 1024)
      *(float4*)(s_w + i) = *(const float4*)(wsrc + i);
  }
  __syncthreads();

  int bid = blockIdx.x;
  int ox0 = (bid & 7) * 16;
  int oy0 = ((bid >> 3) & 15) * 8;
  int oz0 = (bid >> 7) * 8;
  int tx = tid & 7, ty = (tid >> 3) & 7, tz = tid >> 6;   // tz 0..3; z = tz, tz+4

  // acc layout: [0,8)=z0x0, [8,16)=z0x1, [16,24)=z1x0, [24,32)=z1x1
  // each entry = packed pair (y[o=2j], y[o=2j+1])
  unsigned long long acc[32];
#pragma unroll
  for (int j = 0; j < 8; j++){
    unsigned long long bb = *(const unsigned long long*)(s_b + 2*j);
    acc[j] = bb; acc[8 + j] = bb; acc[16 + j] = bb; acc[24 + j] = bb;
  }

#pragma unroll 1
  for (int cc = 0; cc < 2; cc++){
    if (cc) __syncthreads();   // protect s_in overwrite
    // fill halo'd tile for 8 channels with fused BN+LeakyReLU+mask
    for (int idx = tid; idx < 14400; idx += 256){
      int x = idx % 18; int t = idx / 18;
      int y = t % 10;   t /= 10;
      int z = t % 10;   int c = t / 10;
      int gx = ox0 + x - 1, gy = oy0 + y - 1, gz = oz0 + z - 1;
      float val = 0.f;
      if ((unsigned)gx < 128u && (unsigned)gy < 128u && (unsigned)gz < 128u){
        int gp = (gz*128 + gy)*128 + gx;
        if (g_mask[gp]){
          int cg = 8*cc + c;
          float v = fmaf(s_a[cg], in[cg*NVOX + gp], s_c[cg]);
          val = v >= 0.f ? v : SLOPE * v;
        }
      }
      s_in[(c*100 + z*10 + y)*19 + x] = val;
    }
    __syncthreads();

    const float* pin0 = s_in + (tz*10 + ty)*19 + 2*tx;
#pragma unroll 1
    for (int c = 0; c < 8; c++){
      const float* pc = pin0 + c*1900;
      const float* wc = s_w + (8*cc + c)*16;
#pragma unroll
      for (int dz = 0; dz < 3; dz++){
        const float* pz  = pc + dz*190;        // z row (tz+dz)
        const float* pz2 = pz + 760;           // z row (tz+4+dz)
#pragma unroll
        for (int dy = 0; dy < 3; dy++){
          const float* py  = pz  + dy*19;
          const float* py2 = pz2 + dy*19;
          unsigned long long xd[4], xe[4];
#pragma unroll
          for (int i = 0; i < 4; i++){ xd[i] = dup2(py[i]); xe[i] = dup2(py2[i]); }
          const float* wt = wc + (dz*3 + dy)*768;   // tap stride = 256 floats
#pragma unroll
          for (int dx = 0; dx < 3; dx++){
            const ulonglong2* wp = (const ulonglong2*)(wt + dx*256);
            ulonglong2 wq0 = wp[0], wq1 = wp[1], wq2 = wp[2], wq3 = wp[3];
            unsigned long long wv[8] = { wq0.x, wq0.y, wq1.x, wq1.y,
                                         wq2.x, wq2.y, wq3.x, wq3.y };
#pragma unroll
            for (int j = 0; j < 8; j++){
              acc[j]      = ffma2(wv[j], xd[dx],     acc[j]);
              acc[8 + j]  = ffma2(wv[j], xd[dx + 1], acc[8 + j]);
              acc[16 + j] = ffma2(wv[j], xe[dx],     acc[16 + j]);
              acc[24 + j] = ffma2(wv[j], xe[dx + 1], acc[24 + j]);
            }
          }
        }
      }
    }
  }

  int gx0 = ox0 + 2*tx, gy1 = oy0 + ty;
  int gz1 = oz0 + tz, gz2 = gz1 + 4;
  int gp0 = (gz1*128 + gy1)*128 + gx0;
  int gp1 = (gz2*128 + gy1)*128 + gx0;
  uchar2 mu0 = *(const uchar2*)(g_mask + gp0);
  uchar2 mu1 = *(const uchar2*)(g_mask + gp1);
  float m00 = (float)mu0.x, m01 = (float)mu0.y;
  float m10 = (float)mu1.x, m11 = (float)mu1.y;
  float ps[16], pq[16];
#pragma unroll
  for (int j = 0; j < 8; j++){
    float2 a00 = unpack2(acc[j]);        // z0 x0, outputs (2j,2j+1)
    float2 a01 = unpack2(acc[8 + j]);    // z0 x1
    float2 a10 = unpack2(acc[16 + j]);   // z1 x0
    float2 a11 = unpack2(acc[24 + j]);   // z1 x1
    float ya0 = a00.x*m00, ya1 = a01.x*m01;   // o=2j, z0
    float yb0 = a10.x*m10, yb1 = a11.x*m11;   // o=2j, z1
    float yc0 = a00.y*m00, yc1 = a01.y*m01;   // o=2j+1, z0
    float yd0 = a10.y*m10, yd1 = a11.y*m11;   // o=2j+1, z1
    *(float2*)(out + (2*j)*NVOX + gp0)     = make_float2(ya0, ya1);
    *(float2*)(out + (2*j)*NVOX + gp1)     = make_float2(yb0, yb1);
    *(float2*)(out + (2*j + 1)*NVOX + gp0) = make_float2(yc0, yc1);
    *(float2*)(out + (2*j + 1)*NVOX + gp1) = make_float2(yd0, yd1);
    ps[2*j]     = (ya0 + ya1) + (yb0 + yb1);
    pq[2*j]     = (ya0*ya0 + ya1*ya1) + (yb0*yb0 + yb1*yb1);
    ps[2*j + 1] = (yc0 + yc1) + (yd0 + yd1);
    pq[2*j + 1] = (yc0*yc0 + yc1*yc1) + (yd0*yd0 + yd1*yd1);
  }
#pragma unroll
  for (int o = 0; o < 16; o++){
    float s = warp_sum(ps[o]);
    float q = warp_sum(pq[o]);
    if ((tid & 31) == 0){ atomicAdd(&s_red[o], s); atomicAdd(&s_red[16 + o], q); }
  }
  __syncthreads();
  if (tid < 16)      atomicAdd(&sum_c[tid], s_red[tid]);
  else if (tid < 32) atomicAdd(&sq_c[tid - 16], s_red[tid]);
}

// Final: BN4+act+mask on load, 1x1 conv (16->16) + b5, mask, write y + mask plane
__global__ void __launch_bounds__(256) k_final(
    const float* __restrict__ w5, const float* __restrict__ b5,
    const float* __restrict__ gamma_p, const float* __restrict__ beta_p,
    float* __restrict__ outp)
{
  __shared__ float s_w[256];   // [c][o]
  __shared__ float s_a[16], s_c[16], s_b[16];
  const float* in = g_buf0;
  const float* sum_p = g_sum[4];
  const float* sq_p  = g_sq[4];
  int tid = threadIdx.x;
  s_w[tid] = w5[(tid & 15)*16 + (tid >> 4)];
  if (tid < 16){
    float n = (float)g_cnt;
    float mean = sum_p[tid] / n;
    float var = sq_p[tid] / n - mean * mean;
    float a = gamma_p[tid] * rsqrtf(var + EPSV);
    s_a[tid] = a; s_c[tid] = beta_p[tid] - mean * a; s_b[tid] = b5[tid];
  }
  __syncthreads();
  int p = (blockIdx.x*256 + tid) * 4;
  uchar4 mu = *(const uchar4*)(g_mask + p);
  float m[4] = { (float)mu.x, (float)mu.y, (float)mu.z, (float)mu.w };
  float acc[64];
#pragma unroll
  for (int o = 0; o < 16; o++){
    float bb = s_b[o];
    acc[o*4+0] = bb; acc[o*4+1] = bb; acc[o*4+2] = bb; acc[o*4+3] = bb;
  }
#pragma unroll 1
  for (int c = 0; c < 16; c++){
    float4 t4 = *(const float4*)(in + c*NVOX + p);
    float z[4] = { t4.x, t4.y, t4.z, t4.w };
    float a = s_a[c], cc = s_c[c];
#pragma unroll
    for (int v = 0; v < 4; v++){
      float u = fmaf(a, z[v], cc);
      u = u >= 0.f ? u : SLOPE * u;
      z[v] = u * m[v];
    }
    const float4* wp = (const float4*)(s_w + c*16);
    float4 wa = wp[0], wb = wp[1], wc4 = wp[2], wd = wp[3];
    float wv[16] = { wa.x, wa.y, wa.z, wa.w,  wb.x, wb.y, wb.z, wb.w,
                     wc4.x, wc4.y, wc4.z, wc4.w,  wd.x, wd.y, wd.z, wd.w };
#pragma unroll
    for (int o = 0; o < 16; o++)
#pragma unroll
      for (int v = 0; v < 4; v++) acc[o*4+v] = fmaf(wv[o], z[v], acc[o*4+v]);
  }
#pragma unroll
  for (int o = 0; o < 16; o++)
    *(float4*)(outp + o*NVOX + p) = make_float4(acc[o*4+0]*m[0], acc[o*4+1]*m[1],
                                                acc[o*4+2]*m[2], acc[o*4+3]*m[3]);
  *(float4*)(outp + 16*NVOX + p) = make_float4(m[0], m[1], m[2], m[3]);
}

extern "C" void kernel_launch(void* const* d_in, const int* in_sizes, int n_in,
                              void* d_out, int out_size){
  (void)in_sizes; (void)n_in; (void)out_size;
  const float* feat  = (const float*)d_in[0];
  const int*   maski = (const int*)d_in[1];
  const float* w0 = (const float*)d_in[2];
  const float* b0 = (const float*)d_in[3];
  const float* g0 = (const float*)d_in[4];
  const float* be0= (const float*)d_in[5];
  const float* W[4]; const float* Bv[4]; const float* G[4]; const float* BE[4];
  for (int i = 0; i < 4; i++){
    W[i]  = (const float*)d_in[6 + 4*i];
    Bv[i] = (const float*)d_in[7 + 4*i];
    G[i]  = (const float*)d_in[8 + 4*i];
    BE[i] = (const float*)d_in[9 + 4*i];
  }
  const float* w5 = (const float*)d_in[22];
  const float* b5 = (const float*)d_in[23];
  float* outp = (float*)d_out;

  size_t smem = 22192 * sizeof(float);   // 88768 B -> 2 CTAs/SM
  cudaFuncSetAttribute(k_conv, cudaFuncAttributeMaxDynamicSharedMemorySize, (int)smem);

  k_zero<<<1, 128>>>();
  k_pack<<<4, 256>>>(W[0], W[1], W[2], W[3]);
  k_init<<<2048, 256>>>(feat, maski, w0, b0);
  k_conv<<<2048, 256, smem>>>(0, 1, Bv[0], g0,   be0);
  k_conv<<<2048, 256, smem>>>(1, 2, Bv[1], G[0], BE[0]);
  k_conv<<<2048, 256, smem>>>(0, 3, Bv[2], G[1], BE[1]);
  k_conv<<<2048, 256, smem>>>(1, 4, Bv[3], G[2], BE[2]);
  k_final<<<2048, 256>>>(w5, b5, G[3], BE[3], outp);
}

// round 9
// speedup vs baseline: 1.1610x; 1.1610x over previous
#include <cuda_runtime.h>

#define NVOX (128*128*128)
#define EPSV 1e-5f
#define SLOPE 0.01f

// Scratch (device globals: no allocation allowed in kernel_launch)
static __device__ float g_buf0[16*NVOX];   // 128 MB
static __device__ float g_buf1[16*NVOX];   // 128 MB
static __device__ __align__(16) unsigned char g_mask[NVOX];
static __device__ __align__(16) float g_wpack[4][6912];  // weights [tap][c][o]
static __device__ float g_sum[5][16];
static __device__ float g_sq[5][16];
static __device__ int   g_cnt;

__device__ __forceinline__ unsigned long long ffma2(unsigned long long a,
                                                    unsigned long long b,
                                                    unsigned long long c){
  unsigned long long d;
  asm("fma.rn.f32x2 %0, %1, %2, %3;" : "=l"(d) : "l"(a), "l"(b), "l"(c));
  return d;
}
__device__ __forceinline__ unsigned long long dup2(float x){
  unsigned long long d;
  asm("mov.b64 %0, {%1, %1};" : "=l"(d) : "f"(x));
  return d;
}
__device__ __forceinline__ float2 unpack2(unsigned long long v){
  float2 r; asm("mov.b64 {%0, %1}, %2;" : "=f"(r.x), "=f"(r.y) : "l"(v));
  return r;
}

__device__ __forceinline__ float warp_sum(float v){
#pragma unroll
  for (int o = 16; o; o >>= 1) v += __shfl_xor_sync(0xffffffffu, v, o);
  return v;
}

__global__ void k_zero(){
  int t = threadIdx.x;
  if (t < 80){ (&g_sum[0][0])[t] = 0.f; (&g_sq[0][0])[t] = 0.f; }
  if (t == 0) g_cnt = 0;
}

// Repack 3x3x3 weights [o][c][tap] -> [tap][c][o] (one block per layer)
__global__ void k_pack(const float* __restrict__ w1, const float* __restrict__ w2,
                       const float* __restrict__ w3, const float* __restrict__ w4){
  const float* w = blockIdx.x == 0 ? w1 : blockIdx.x == 1 ? w2 :
                   blockIdx.x == 2 ? w3 : w4;
  for (int i = threadIdx.x; i < 6912; i += 256){
    int o = i & 15, c = (i >> 4) & 15, tap = i >> 8;
    g_wpack[blockIdx.x][i] = w[(o*16 + c)*27 + tap];
  }
}

// Layer 0: mask gen + active count + 1x1 conv (4->16) + masked stats
__global__ void __launch_bounds__(256) k_init(
    const float* __restrict__ feat, const int* __restrict__ maski,
    const float* __restrict__ w0, const float* __restrict__ b0)
{
  __shared__ float s_w[64];   // [c][o]
  __shared__ float s_b[16];
  __shared__ float s_red[32];
  __shared__ int s_cnt;
  int tid = threadIdx.x;
  if (tid < 64) s_w[tid] = w0[(tid & 15) * 4 + (tid >> 4)];
  if (tid < 16) s_b[tid] = b0[tid];
  if (tid < 32) s_red[tid] = 0.f;
  if (tid == 0) s_cnt = 0;
  __syncthreads();

  int p = (blockIdx.x * 256 + tid) * 4;
  float xf[4][4];
#pragma unroll
  for (int c = 0; c < 4; c++){
    float4 t4 = *(const float4*)(feat + c * NVOX + p);
    xf[c][0] = t4.x; xf[c][1] = t4.y; xf[c][2] = t4.z; xf[c][3] = t4.w;
  }
  int4 mi = *(const int4*)(maski + p);
  float m[4] = { mi.x > 0 ? 1.f : 0.f, mi.y > 0 ? 1.f : 0.f,
                 mi.z > 0 ? 1.f : 0.f, mi.w > 0 ? 1.f : 0.f };
  *(uchar4*)(g_mask + p) = make_uchar4((unsigned char)m[0], (unsigned char)m[1],
                                       (unsigned char)m[2], (unsigned char)m[3]);
  int cnt = (int)(m[0] + m[1] + m[2] + m[3]);

  float ps[16], pq[16];
#pragma unroll
  for (int o = 0; o < 16; o++){
    float y[4];
#pragma unroll
    for (int v = 0; v < 4; v++){
      float a = s_b[o];
#pragma unroll
      for (int c = 0; c < 4; c++) a = fmaf(s_w[c*16 + o], xf[c][v], a);
      y[v] = a * m[v];
    }
    *(float4*)(g_buf0 + o*NVOX + p) = make_float4(y[0], y[1], y[2], y[3]);
    ps[o] = (y[0] + y[1]) + (y[2] + y[3]);
    pq[o] = (y[0]*y[0] + y[1]*y[1]) + (y[2]*y[2] + y[3]*y[3]);
  }
#pragma unroll
  for (int o = 0; o < 16; o++){
    float s = warp_sum(ps[o]);
    float q = warp_sum(pq[o]);
    if ((tid & 31) == 0){ atomicAdd(&s_red[o], s); atomicAdd(&s_red[16 + o], q); }
  }
  {
    int c2 = cnt;
#pragma unroll
    for (int o = 16; o; o >>= 1) c2 += __shfl_xor_sync(0xffffffffu, c2, o);
    if ((tid & 31) == 0) atomicAdd(&s_cnt, c2);
  }
  __syncthreads();
  if (tid < 16)      atomicAdd(&g_sum[0][tid], s_red[tid]);
  else if (tid < 32) atomicAdd(&g_sq[0][tid - 16], s_red[tid]);
  if (tid == 0) atomicAdd(&g_cnt, s_cnt);
}

// 3x3x3 subm conv, fused BN+LeakyReLU+mask on smem fill, masked raw output,
// stats accumulated. R5 tiling: 256 threads, tile 16x8x4, 2 voxels/thread,
// FFMA2-packed over output-channel pairs. 4-channel chunks with
// double-buffered s_in so the fill LDGs of chunk k+1 overlap compute of k.
// smem layout (floats): s_w[0,6912) s_inA[6912,11472) s_inB[11472,16032)
//   s_a[16032,16048) s_c[16048,16064) s_b[16064,16080) s_red[16080,16112)
__global__ void __launch_bounds__(256, 3) k_conv(
    int dir, int stage,
    const float* __restrict__ b,
    const float* __restrict__ gamma_p, const float* __restrict__ beta_p)
{
  extern __shared__ float sm[];
  float* s_w   = sm;
  float* s_inA = sm + 6912;
  float* s_inB = sm + 11472;
  float* s_a   = sm + 16032;
  float* s_c   = s_a + 16;
  float* s_b   = s_c + 16;     // float offset 16064 (8B-aligned)
  float* s_red = s_b + 16;     // [16080,16112)

  const float* in  = dir ? g_buf1 : g_buf0;
  float*       out = dir ? g_buf0 : g_buf1;
  const float* sum_p = g_sum[stage - 1];
  const float* sq_p  = g_sq[stage - 1];
  float* sum_c = g_sum[stage];
  float* sq_c  = g_sq[stage];

  int tid = threadIdx.x;
  if (tid < 16){
    float n = (float)g_cnt;
    float mean = sum_p[tid] / n;
    float var = sq_p[tid] / n - mean * mean;
    float a = gamma_p[tid] * rsqrtf(var + EPSV);
    s_a[tid] = a;
    s_c[tid] = beta_p[tid] - mean * a;
    s_b[tid] = b[tid];
  }
  if (tid < 32) s_red[tid] = 0.f;
  {
    const float* wsrc = g_wpack[stage - 1];
    for (int i = tid * 4; i < 6912; i += 1024)
      *(float4*)(s_w + i) = *(const float4*)(wsrc + i);
  }

  int bid = blockIdx.x;
  int ox0 = (bid & 7) * 16;
  int oy0 = ((bid >> 3) & 15) * 8;
  int oz0 = (bid >> 7) * 4;
  int tx = tid & 7, ty = (tid >> 3) & 7, tz = tid >> 6;

  // fill one 4-channel chunk (channels 4*cc .. 4*cc+3) into buf
  auto fill = [&](int cc, float* buf){
    for (int idx = tid; idx < 4320; idx += 256){
      int x = idx % 18; int t = idx / 18;
      int y = t % 10;   t /= 10;
      int z = t % 6;    int c = t / 6;
      int gx = ox0 + x - 1, gy = oy0 + y - 1, gz = oz0 + z - 1;
      float val = 0.f;
      if ((unsigned)gx < 128u && (unsigned)gy < 128u && (unsigned)gz < 128u){
        int gp = (gz*128 + gy)*128 + gx;
        if (g_mask[gp]){
          int cg = 4*cc + c;
          float v = fmaf(s_a[cg], in[cg*NVOX + gp], s_c[cg]);
          val = v >= 0.f ? v : SLOPE * v;
        }
      }
      buf[(c*60 + z*10 + y)*19 + x] = val;
    }
  };

  __syncthreads();          // s_a/s_c ready before first fill
  fill(0, s_inA);
  __syncthreads();          // chunk 0 visible

  // acc[v*8 + j] = packed pair (y[o=2j], y[o=2j+1]) for voxel v
  unsigned long long acc[16];
#pragma unroll
  for (int j = 0; j < 8; j++){
    unsigned long long bb = *(const unsigned long long*)(s_b + 2*j);
    acc[j] = bb; acc[8 + j] = bb;
  }

#pragma unroll 1
  for (int cc = 0; cc < 4; cc++){
    float* cur = (cc & 1) ? s_inB : s_inA;
    float* nxt = (cc & 1) ? s_inA : s_inB;
    if (cc < 3) fill(cc + 1, nxt);   // overlap next fill with this compute

    const float* pin0 = cur + (tz*10 + ty)*19 + 2*tx;
#pragma unroll 2
    for (int c = 0; c < 4; c++){
      const float* pc = pin0 + c*1140;
      const float* wc = s_w + (4*cc + c)*16;
#pragma unroll
      for (int dz = 0; dz < 3; dz++){
        const float* pz = pc + dz*190;
#pragma unroll
        for (int dy = 0; dy < 3; dy++){
          const float* py = pz + dy*19;
          unsigned long long xd[4];
#pragma unroll
          for (int i = 0; i < 4; i++) xd[i] = dup2(py[i]);
          const float* wt = wc + (dz*3 + dy)*768;   // tap stride = 256 floats
#pragma unroll
          for (int dx = 0; dx < 3; dx++){
            const ulonglong2* wp = (const ulonglong2*)(wt + dx*256);
            ulonglong2 wq0 = wp[0], wq1 = wp[1], wq2 = wp[2], wq3 = wp[3];
            unsigned long long wv[8] = { wq0.x, wq0.y, wq1.x, wq1.y,
                                         wq2.x, wq2.y, wq3.x, wq3.y };
#pragma unroll
            for (int j = 0; j < 8; j++){
              acc[j]     = ffma2(wv[j], xd[dx],     acc[j]);
              acc[8 + j] = ffma2(wv[j], xd[dx + 1], acc[8 + j]);
            }
          }
        }
      }
    }
    __syncthreads();   // next chunk fully written & cur no longer needed
  }

  int gx0 = ox0 + 2*tx, gy1 = oy0 + ty, gz1 = oz0 + tz;
  int gp = (gz1*128 + gy1)*128 + gx0;
  uchar2 mu = *(const uchar2*)(g_mask + gp);
  float m0 = (float)mu.x, m1 = (float)mu.y;
  float ps[16], pq[16];
#pragma unroll
  for (int j = 0; j < 8; j++){
    float2 a0 = unpack2(acc[j]);       // voxel 0, outputs (2j, 2j+1)
    float2 a1 = unpack2(acc[8 + j]);   // voxel 1
    float y00 = a0.x*m0, y10 = a1.x*m1;   // o = 2j
    float y01 = a0.y*m0, y11 = a1.y*m1;   // o = 2j+1
    *(float2*)(out + (2*j)*NVOX + gp)     = make_float2(y00, y10);
    *(float2*)(out + (2*j + 1)*NVOX + gp) = make_float2(y01, y11);
    ps[2*j]     = y00 + y10;  pq[2*j]     = y00*y00 + y10*y10;
    ps[2*j + 1] = y01 + y11;  pq[2*j + 1] = y01*y01 + y11*y11;
  }
#pragma unroll
  for (int o = 0; o < 16; o++){
    float s = warp_sum(ps[o]);
    float q = warp_sum(pq[o]);
    if ((tid & 31) == 0){ atomicAdd(&s_red[o], s); atomicAdd(&s_red[16 + o], q); }
  }
  __syncthreads();
  if (tid < 16)      atomicAdd(&sum_c[tid], s_red[tid]);
  else if (tid < 32) atomicAdd(&sq_c[tid - 16], s_red[tid]);
}

// Final: BN4+act+mask on load, 1x1 conv (16->16) + b5, mask, write y + mask plane
__global__ void __launch_bounds__(256) k_final(
    const float* __restrict__ w5, const float* __restrict__ b5,
    const float* __restrict__ gamma_p, const float* __restrict__ beta_p,
    float* __restrict__ outp)
{
  __shared__ float s_w[256];   // [c][o]
  __shared__ float s_a[16], s_c[16], s_b[16];
  const float* in = g_buf0;
  const float* sum_p = g_sum[4];
  const float* sq_p  = g_sq[4];
  int tid = threadIdx.x;
  s_w[tid] = w5[(tid & 15)*16 + (tid >> 4)];
  if (tid < 16){
    float n = (float)g_cnt;
    float mean = sum_p[tid] / n;
    float var = sq_p[tid] / n - mean * mean;
    float a = gamma_p[tid] * rsqrtf(var + EPSV);
    s_a[tid] = a; s_c[tid] = beta_p[tid] - mean * a; s_b[tid] = b5[tid];
  }
  __syncthreads();
  int p = (blockIdx.x*256 + tid) * 4;
  uchar4 mu = *(const uchar4*)(g_mask + p);
  float m[4] = { (float)mu.x, (float)mu.y, (float)mu.z, (float)mu.w };
  float acc[64];
#pragma unroll
  for (int o = 0; o < 16; o++){
    float bb = s_b[o];
    acc[o*4+0] = bb; acc[o*4+1] = bb; acc[o*4+2] = bb; acc[o*4+3] = bb;
  }
#pragma unroll 1
  for (int c = 0; c < 16; c++){
    float4 t4 = *(const float4*)(in + c*NVOX + p);
    float z[4] = { t4.x, t4.y, t4.z, t4.w };
    float a = s_a[c], cc = s_c[c];
#pragma unroll
    for (int v = 0; v < 4; v++){
      float u = fmaf(a, z[v], cc);
      u = u >= 0.f ? u : SLOPE * u;
      z[v] = u * m[v];
    }
    const float4* wp = (const float4*)(s_w + c*16);
    float4 wa = wp[0], wb = wp[1], wc4 = wp[2], wd = wp[3];
    float wv[16] = { wa.x, wa.y, wa.z, wa.w,  wb.x, wb.y, wb.z, wb.w,
                     wc4.x, wc4.y, wc4.z, wc4.w,  wd.x, wd.y, wd.z, wd.w };
#pragma unroll
    for (int o = 0; o < 16; o++)
#pragma unroll
      for (int v = 0; v < 4; v++) acc[o*4+v] = fmaf(wv[o], z[v], acc[o*4+v]);
  }
#pragma unroll
  for (int o = 0; o < 16; o++)
    *(float4*)(outp + o*NVOX + p) = make_float4(acc[o*4+0]*m[0], acc[o*4+1]*m[1],
                                                acc[o*4+2]*m[2], acc[o*4+3]*m[3]);
  *(float4*)(outp + 16*NVOX + p) = make_float4(m[0], m[1], m[2], m[3]);
}

extern "C" void kernel_launch(void* const* d_in, const int* in_sizes, int n_in,
                              void* d_out, int out_size){
  (void)in_sizes; (void)n_in; (void)out_size;
  const float* feat  = (const float*)d_in[0];
  const int*   maski = (const int*)d_in[1];
  const float* w0 = (const float*)d_in[2];
  const float* b0 = (const float*)d_in[3];
  const float* g0 = (const float*)d_in[4];
  const float* be0= (const float*)d_in[5];
  const float* W[4]; const float* Bv[4]; const float* G[4]; const float* BE[4];
  for (int i = 0; i < 4; i++){
    W[i]  = (const float*)d_in[6 + 4*i];
    Bv[i] = (const float*)d_in[7 + 4*i];
    G[i]  = (const float*)d_in[8 + 4*i];
    BE[i] = (const float*)d_in[9 + 4*i];
  }
  const float* w5 = (const float*)d_in[22];
  const float* b5 = (const float*)d_in[23];
  float* outp = (float*)d_out;

  size_t smem = 16128 * sizeof(float);   // 64512 B -> 3 CTAs/SM
  cudaFuncSetAttribute(k_conv, cudaFuncAttributeMaxDynamicSharedMemorySize, (int)smem);

  k_zero<<<1, 128>>>();
  k_pack<<<4, 256>>>(W[0], W[1], W[2], W[3]);
  k_init<<<2048, 256>>>(feat, maski, w0, b0);
  k_conv<<<4096, 256, smem>>>(0, 1, Bv[0], g0,   be0);
  k_conv<<<4096, 256, smem>>>(1, 2, Bv[1], G[0], BE[0]);
  k_conv<<<4096, 256, smem>>>(0, 3, Bv[2], G[1], BE[1]);
  k_conv<<<4096, 256, smem>>>(1, 4, Bv[3], G[2], BE[2]);
  k_final<<<2048, 256>>>(w5, b5, G[3], BE[3], outp);
}

// round 12
// speedup vs baseline: 1.2194x; 1.0503x over previous
#include <cuda_runtime.h>

#define NVOX (128*128*128)
#define EPSV 1e-5f
#define SLOPE 0.01f

// Scratch (device globals: no allocation allowed in kernel_launch)
static __device__ float g_buf0[16*NVOX];   // 128 MB
static __device__ float g_buf1[16*NVOX];   // 128 MB
static __device__ __align__(16) unsigned char g_mask[NVOX];
static __device__ __align__(16) float g_wpack[4][6912];  // weights [tap][c][o]
static __device__ float g_sum[5][16];
static __device__ float g_sq[5][16];
static __device__ int   g_cnt;

__device__ __forceinline__ unsigned long long ffma2(unsigned long long a,
                                                    unsigned long long b,
                                                    unsigned long long c){
  unsigned long long d;
  asm("fma.rn.f32x2 %0, %1, %2, %3;" : "=l"(d) : "l"(a), "l"(b), "l"(c));
  return d;
}
__device__ __forceinline__ unsigned long long dup2(float x){
  unsigned long long d;
  asm("mov.b64 %0, {%1, %1};" : "=l"(d) : "f"(x));
  return d;
}
__device__ __forceinline__ float2 unpack2(unsigned long long v){
  float2 r; asm("mov.b64 {%0, %1}, %2;" : "=f"(r.x), "=f"(r.y) : "l"(v));
  return r;
}

__device__ __forceinline__ float warp_sum(float v){
#pragma unroll
  for (int o = 16; o; o >>= 1) v += __shfl_xor_sync(0xffffffffu, v, o);
  return v;
}

__global__ void k_zero(){
  int t = threadIdx.x;
  if (t < 80){ (&g_sum[0][0])[t] = 0.f; (&g_sq[0][0])[t] = 0.f; }
  if (t == 0) g_cnt = 0;
}

// Repack 3x3x3 weights [o][c][tap] -> [tap][c][o] (one block per layer)
__global__ void k_pack(const float* __restrict__ w1, const float* __restrict__ w2,
                       const float* __restrict__ w3, const float* __restrict__ w4){
  const float* w = blockIdx.x == 0 ? w1 : blockIdx.x == 1 ? w2 :
                   blockIdx.x == 2 ? w3 : w4;
  for (int i = threadIdx.x; i < 6912; i += 256){
    int o = i & 15, c = (i >> 4) & 15, tap = i >> 8;
    g_wpack[blockIdx.x][i] = w[(o*16 + c)*27 + tap];
  }
}

// Layer 0: mask gen + active count + 1x1 conv (4->16) + masked stats
__global__ void __launch_bounds__(256) k_init(
    const float* __restrict__ feat, const int* __restrict__ maski,
    const float* __restrict__ w0, const float* __restrict__ b0)
{
  __shared__ float s_w[64];   // [c][o]
  __shared__ float s_b[16];
  __shared__ float s_red[32];
  __shared__ int s_cnt;
  int tid = threadIdx.x;
  if (tid < 64) s_w[tid] = w0[(tid & 15) * 4 + (tid >> 4)];
  if (tid < 16) s_b[tid] = b0[tid];
  if (tid < 32) s_red[tid] = 0.f;
  if (tid == 0) s_cnt = 0;
  __syncthreads();

  int p = (blockIdx.x * 256 + tid) * 4;
  float xf[4][4];
#pragma unroll
  for (int c = 0; c < 4; c++){
    float4 t4 = *(const float4*)(feat + c * NVOX + p);
    xf[c][0] = t4.x; xf[c][1] = t4.y; xf[c][2] = t4.z; xf[c][3] = t4.w;
  }
  int4 mi = *(const int4*)(maski + p);
  float m[4] = { mi.x > 0 ? 1.f : 0.f, mi.y > 0 ? 1.f : 0.f,
                 mi.z > 0 ? 1.f : 0.f, mi.w > 0 ? 1.f : 0.f };
  *(uchar4*)(g_mask + p) = make_uchar4((unsigned char)m[0], (unsigned char)m[1],
                                       (unsigned char)m[2], (unsigned char)m[3]);
  int cnt = (int)(m[0] + m[1] + m[2] + m[3]);

  float ps[16], pq[16];
#pragma unroll
  for (int o = 0; o < 16; o++){
    float y[4];
#pragma unroll
    for (int v = 0; v < 4; v++){
      float a = s_b[o];
#pragma unroll
      for (int c = 0; c < 4; c++) a = fmaf(s_w[c*16 + o], xf[c][v], a);
      y[v] = a * m[v];
    }
    *(float4*)(g_buf0 + o*NVOX + p) = make_float4(y[0], y[1], y[2], y[3]);
    ps[o] = (y[0] + y[1]) + (y[2] + y[3]);
    pq[o] = (y[0]*y[0] + y[1]*y[1]) + (y[2]*y[2] + y[3]*y[3]);
  }
#pragma unroll
  for (int o = 0; o < 16; o++){
    float s = warp_sum(ps[o]);
    float q = warp_sum(pq[o]);
    if ((tid & 31) == 0){ atomicAdd(&s_red[o], s); atomicAdd(&s_red[16 + o], q); }
  }
  {
    int c2 = cnt;
#pragma unroll
    for (int o = 16; o; o >>= 1) c2 += __shfl_xor_sync(0xffffffffu, c2, o);
    if ((tid & 31) == 0) atomicAdd(&s_cnt, c2);
  }
  __syncthreads();
  if (tid < 16)      atomicAdd(&g_sum[0][tid], s_red[tid]);
  else if (tid < 32) atomicAdd(&g_sq[0][tid - 16], s_red[tid]);
  if (tid == 0) atomicAdd(&g_cnt, s_cnt);
}

// 3x3x3 subm conv, fused BN+LeakyReLU+mask on smem fill, masked raw output,
// stats accumulated. 256 threads, tile 16x8x4, 2 voxels/thread, FFMA2-packed
// over output-channel pairs. 4-channel single-buffered chunks; smem trimmed to
// 46.2 KB and regs capped at 64 so 4 CTAs/SM (32 warps) fit -> latency hiding.
// smem (floats): s_w[0,6912) s_in[6912,11472) s_a[11472,11488)
//   s_c[11488,11504) s_b[11504,11520) s_red[11520,11552)  -> alloc 11552
__global__ void __launch_bounds__(256, 4) k_conv(
    int dir, int stage,
    const float* __restrict__ b,
    const float* __restrict__ gamma_p, const float* __restrict__ beta_p)
{
  extern __shared__ float sm[];
  float* s_w   = sm;
  float* s_in  = sm + 6912;
  float* s_a   = sm + 11472;
  float* s_c   = s_a + 16;
  float* s_b   = s_c + 16;     // float offset 11504 (8B-aligned)
  float* s_red = s_b + 16;     // [11520,11552)

  const float* in  = dir ? g_buf1 : g_buf0;
  float*       out = dir ? g_buf0 : g_buf1;
  const float* sum_p = g_sum[stage - 1];
  const float* sq_p  = g_sq[stage - 1];
  float* sum_c = g_sum[stage];
  float* sq_c  = g_sq[stage];

  int tid = threadIdx.x;
  if (tid < 16){
    float n = (float)g_cnt;
    float mean = sum_p[tid] / n;
    float var = sq_p[tid] / n - mean * mean;
    float a = gamma_p[tid] * rsqrtf(var + EPSV);
    s_a[tid] = a;
    s_c[tid] = beta_p[tid] - mean * a;
    s_b[tid] = b[tid];
  }
  if (tid < 32) s_red[tid] = 0.f;
  {
    const float* wsrc = g_wpack[stage - 1];
    for (int i = tid * 4; i < 6912; i += 1024)
      *(float4*)(s_w + i) = *(const float4*)(wsrc + i);
  }

  int bid = blockIdx.x;
  int ox0 = (bid & 7) * 16;
  int oy0 = ((bid >> 3) & 15) * 8;
  int oz0 = (bid >> 7) * 4;
  int tx = tid & 7, ty = (tid >> 3) & 7, tz = tid >> 6;

  __syncthreads();          // s_a/s_c/s_w ready

  // acc[v*8 + j] = packed pair (y[o=2j], y[o=2j+1]) for voxel v
  unsigned long long acc[16];
#pragma unroll
  for (int j = 0; j < 8; j++){
    unsigned long long bb = *(const unsigned long long*)(s_b + 2*j);
    acc[j] = bb; acc[8 + j] = bb;
  }

#pragma unroll 1
  for (int cc = 0; cc < 4; cc++){
    if (cc) __syncthreads();   // previous compute done before overwrite
    // fill halo'd tile for channels 4*cc..4*cc+3 with fused BN+LeakyReLU+mask
    for (int idx = tid; idx < 4320; idx += 256){
      int x = idx % 18; int t = idx / 18;
      int y = t % 10;   t /= 10;
      int z = t % 6;    int c = t / 6;
      int gx = ox0 + x - 1, gy = oy0 + y - 1, gz = oz0 + z - 1;
      float val = 0.f;
      if ((unsigned)gx < 128u && (unsigned)gy < 128u && (unsigned)gz < 128u){
        int gp = (gz*128 + gy)*128 + gx;
        if (g_mask[gp]){
          int cg = 4*cc + c;
          float v = fmaf(s_a[cg], in[cg*NVOX + gp], s_c[cg]);
          val = v >= 0.f ? v : SLOPE * v;
        }
      }
      s_in[(c*60 + z*10 + y)*19 + x] = val;
    }
    __syncthreads();           // fill visible

    const float* pin0 = s_in + (tz*10 + ty)*19 + 2*tx;
#pragma unroll 1
    for (int c = 0; c < 4; c++){
      const float* pc = pin0 + c*1140;
      const float* wc = s_w + (4*cc + c)*16;
#pragma unroll
      for (int dz = 0; dz < 3; dz++){
        const float* pz = pc + dz*190;
#pragma unroll
        for (int dy = 0; dy < 3; dy++){
          const float* py = pz + dy*19;
          unsigned long long xd[4];
#pragma unroll
          for (int i = 0; i < 4; i++) xd[i] = dup2(py[i]);
          const float* wt = wc + (dz*3 + dy)*768;   // tap stride = 256 floats
#pragma unroll
          for (int dx = 0; dx < 3; dx++){
            const ulonglong2* wp = (const ulonglong2*)(wt + dx*256);
            // half 1: outputs 0..7 (pairs j=0..3) — small live weight set
            {
              ulonglong2 wq0 = wp[0], wq1 = wp[1];
              unsigned long long wv[4] = { wq0.x, wq0.y, wq1.x, wq1.y };
#pragma unroll
              for (int j = 0; j < 4; j++){
                acc[j]     = ffma2(wv[j], xd[dx],     acc[j]);
                acc[8 + j] = ffma2(wv[j], xd[dx + 1], acc[8 + j]);
              }
            }
            // half 2: outputs 8..15 (pairs j=4..7)
            {
              ulonglong2 wq2 = wp[2], wq3 = wp[3];
              unsigned long long wv[4] = { wq2.x, wq2.y, wq3.x, wq3.y };
#pragma unroll
              for (int j = 0; j < 4; j++){
                acc[4 + j]  = ffma2(wv[j], xd[dx],     acc[4 + j]);
                acc[12 + j] = ffma2(wv[j], xd[dx + 1], acc[12 + j]);
              }
            }
          }
        }
      }
    }
  }

  int gx0 = ox0 + 2*tx, gy1 = oy0 + ty, gz1 = oz0 + tz;
  int gp = (gz1*128 + gy1)*128 + gx0;
  uchar2 mu = *(const uchar2*)(g_mask + gp);
  float m0 = (float)mu.x, m1 = (float)mu.y;
  float ps[16], pq[16];
#pragma unroll
  for (int j = 0; j < 8; j++){
    float2 a0 = unpack2(acc[j]);       // voxel 0, outputs (2j, 2j+1)
    float2 a1 = unpack2(acc[8 + j]);   // voxel 1
    float y00 = a0.x*m0, y10 = a1.x*m1;   // o = 2j
    float y01 = a0.y*m0, y11 = a1.y*m1;   // o = 2j+1
    *(float2*)(out + (2*j)*NVOX + gp)     = make_float2(y00, y10);
    *(float2*)(out + (2*j + 1)*NVOX + gp) = make_float2(y01, y11);
    ps[2*j]     = y00 + y10;  pq[2*j]     = y00*y00 + y10*y10;
    ps[2*j + 1] = y01 + y11;  pq[2*j + 1] = y01*y01 + y11*y11;
  }
#pragma unroll
  for (int o = 0; o < 16; o++){
    float s = warp_sum(ps[o]);
    float q = warp_sum(pq[o]);
    if ((tid & 31) == 0){ atomicAdd(&s_red[o], s); atomicAdd(&s_red[16 + o], q); }
  }
  __syncthreads();
  if (tid < 16)      atomicAdd(&sum_c[tid], s_red[tid]);
  else if (tid < 32) atomicAdd(&sq_c[tid - 16], s_red[tid]);
}

// Final: BN4+act+mask on load, 1x1 conv (16->16) + b5, mask, write y + mask plane
__global__ void __launch_bounds__(256) k_final(
    const float* __restrict__ w5, const float* __restrict__ b5,
    const float* __restrict__ gamma_p, const float* __restrict__ beta_p,
    float* __restrict__ outp)
{
  __shared__ float s_w[256];   // [c][o]
  __shared__ float s_a[16], s_c[16], s_b[16];
  const float* in = g_buf0;
  const float* sum_p = g_sum[4];
  const float* sq_p  = g_sq[4];
  int tid = threadIdx.x;
  s_w[tid] = w5[(tid & 15)*16 + (tid >> 4)];
  if (tid < 16){
    float n = (float)g_cnt;
    float mean = sum_p[tid] / n;
    float var = sq_p[tid] / n - mean * mean;
    float a = gamma_p[tid] * rsqrtf(var + EPSV);
    s_a[tid] = a; s_c[tid] = beta_p[tid] - mean * a; s_b[tid] = b5[tid];
  }
  __syncthreads();
  int p = (blockIdx.x*256 + tid) * 4;
  uchar4 mu = *(const uchar4*)(g_mask + p);
  float m[4] = { (float)mu.x, (float)mu.y, (float)mu.z, (float)mu.w };
  float acc[64];
#pragma unroll
  for (int o = 0; o < 16; o++){
    float bb = s_b[o];
    acc[o*4+0] = bb; acc[o*4+1] = bb; acc[o*4+2] = bb; acc[o*4+3] = bb;
  }
#pragma unroll 1
  for (int c = 0; c < 16; c++){
    float4 t4 = *(const float4*)(in + c*NVOX + p);
    float z[4] = { t4.x, t4.y, t4.z, t4.w };
    float a = s_a[c], cc = s_c[c];
#pragma unroll
    for (int v = 0; v < 4; v++){
      float u = fmaf(a, z[v], cc);
      u = u >= 0.f ? u : SLOPE * u;
      z[v] = u * m[v];
    }
    const float4* wp = (const float4*)(s_w + c*16);
    float4 wa = wp[0], wb = wp[1], wc4 = wp[2], wd = wp[3];
    float wv[16] = { wa.x, wa.y, wa.z, wa.w,  wb.x, wb.y, wb.z, wb.w,
                     wc4.x, wc4.y, wc4.z, wc4.w,  wd.x, wd.y, wd.z, wd.w };
#pragma unroll
    for (int o = 0; o < 16; o++)
#pragma unroll
      for (int v = 0; v < 4; v++) acc[o*4+v] = fmaf(wv[o], z[v], acc[o*4+v]);
  }
#pragma unroll
  for (int o = 0; o < 16; o++)
    *(float4*)(outp + o*NVOX + p) = make_float4(acc[o*4+0]*m[0], acc[o*4+1]*m[1],
                                                acc[o*4+2]*m[2], acc[o*4+3]*m[3]);
  *(float4*)(outp + 16*NVOX + p) = make_float4(m[0], m[1], m[2], m[3]);
}

extern "C" void kernel_launch(void* const* d_in, const int* in_sizes, int n_in,
                              void* d_out, int out_size){
  (void)in_sizes; (void)n_in; (void)out_size;
  const float* feat  = (const float*)d_in[0];
  const int*   maski = (const int*)d_in[1];
  const float* w0 = (const float*)d_in[2];
  const float* b0 = (const float*)d_in[3];
  const float* g0 = (const float*)d_in[4];
  const float* be0= (const float*)d_in[5];
  const float* W[4]; const float* Bv[4]; const float* G[4]; const float* BE[4];
  for (int i = 0; i < 4; i++){
    W[i]  = (const float*)d_in[6 + 4*i];
    Bv[i] = (const float*)d_in[7 + 4*i];
    G[i]  = (const float*)d_in[8 + 4*i];
    BE[i] = (const float*)d_in[9 + 4*i];
  }
  const float* w5 = (const float*)d_in[22];
  const float* b5 = (const float*)d_in[23];
  float* outp = (float*)d_out;

  size_t smem = 11552 * sizeof(float);   // 46208 B -> 4 CTAs/SM
  cudaFuncSetAttribute(k_conv, cudaFuncAttributeMaxDynamicSharedMemorySize, (int)smem);

  k_zero<<<1, 128>>>();
  k_pack<<<4, 256>>>(W[0], W[1], W[2], W[3]);
  k_init<<<2048, 256>>>(feat, maski, w0, b0);
  k_conv<<<4096, 256, smem>>>(0, 1, Bv[0], g0,   be0);
  k_conv<<<4096, 256, smem>>>(1, 2, Bv[1], G[0], BE[0]);
  k_conv<<<4096, 256, smem>>>(0, 3, Bv[2], G[1], BE[1]);
  k_conv<<<4096, 256, smem>>>(1, 4, Bv[3], G[2], BE[2]);
  k_final<<<2048, 256>>>(w5, b5, G[3], BE[3], outp);
}